// round 2
// baseline (speedup 1.0000x reference)
#include <cuda_runtime.h>
#include <cstdint>

// KPConv fused kernel: M=50000 queries, H=32 neighbors, K=15 kernel points,
// Cin=Cout=64. One block handles QT=16 queries end-to-end in shared memory.
//
// neighbor_indices dtype is auto-detected (int32 vs int64) by a probe kernel:
// int64 values in [0, N] have all-zero high words; int32 random indices do not.

#define QT 16
#define HN 32
#define KK 15
#define KP 16        // K padded to 16 for float4 reads
#define CC 64        // Cin == Cout
#define NTHREADS 256

__device__ int g_idx64;   // 1 if neighbor_indices is int64, 0 if int32

__global__ void init_flag_kernel() { g_idx64 = 1; }

__global__ void probe_idx_kernel(const int* __restrict__ words, int nwords) {
    int i = blockIdx.x * blockDim.x + threadIdx.x;
    int pos = 2 * i + 1;                 // odd 32-bit words = int64 high halves
    if (pos < nwords && words[pos] != 0) g_idx64 = 0;  // racy same-value write: fine
}

struct __align__(16) Smem {
    float infl[QT][HN][KP];     // 32768 B, 16B-aligned rows
    float weighted[QT][KK][CC]; // 61440 B
    float kp[KK][3];            // 180 B
    int   sidx[QT][HN];         // 2048 B
    unsigned vmask[QT];         // 64 B
    float nnum[QT];             // 64 B
};

__global__ __launch_bounds__(NTHREADS, 2)
void kpconv_kernel(const float* __restrict__ q_points,
                   const float* __restrict__ s_points,
                   const float* __restrict__ s_feats,
                   const void* __restrict__ nbr_idx_raw,
                   const float* __restrict__ kernel_points,
                   const float* __restrict__ weights,
                   float* __restrict__ out,
                   int M, int N)
{
    extern __shared__ __align__(16) char smem_raw[];
    Smem& sm = *reinterpret_cast<Smem*>(smem_raw);
    const int tid = threadIdx.x;
    const int m0 = blockIdx.x * QT;
    const int idx64 = g_idx64;

    // ---- load kernel points ----
    if (tid < KK * 3) {
        reinterpret_cast<float*>(sm.kp)[tid] = kernel_points[tid];
    }
    __syncthreads();

    // ---- Stage A: influence + validity mask ----
    // warp handles one query per pass: (m, h) = (p*8 + tid/32, tid%32)
    {
        const int lane = tid & 31;
        const int wgrp = tid >> 5;
        #pragma unroll
        for (int p = 0; p < 2; ++p) {
            const int ml = p * 8 + wgrp;
            const int m = m0 + ml;
            bool valid = false;
            int si = 0;
            float rx = 0.f, ry = 0.f, rz = 0.f;
            if (m < M) {
                long long gi;
                if (idx64)
                    gi = reinterpret_cast<const long long*>(nbr_idx_raw)[(long long)m * HN + lane];
                else
                    gi = reinterpret_cast<const int*>(nbr_idx_raw)[(long long)m * HN + lane];
                if (gi < (long long)N) { valid = true; si = (int)gi; }
            }
            sm.sidx[ml][lane] = si;
            if (valid) {
                rx = s_points[si * 3 + 0] - q_points[m * 3 + 0];
                ry = s_points[si * 3 + 1] - q_points[m * 3 + 1];
                rz = s_points[si * 3 + 2] - q_points[m * 3 + 2];
            }
            #pragma unroll
            for (int k = 0; k < KK; ++k) {
                float dx = rx - sm.kp[k][0];
                float dy = ry - sm.kp[k][1];
                float dz = rz - sm.kp[k][2];
                float d2 = dx * dx + dy * dy + dz * dz;
                float inf = fmaxf(1.0f - sqrtf(d2), 0.0f);  // SIGMA = 1
                sm.infl[ml][lane][k] = valid ? inf : 0.0f;
            }
            sm.infl[ml][lane][KK] = 0.0f;  // pad
            unsigned bal = __ballot_sync(0xffffffffu, valid);
            if (lane == 0) sm.vmask[ml] = bal;
        }
    }
    __syncthreads();

    // ---- Stage B: weighted[m][k][c] = sum_h infl[m][h][k] * feat[idx(m,h)][c]
    //      plus neighbor count (feat-sum > 0) via warp butterfly reduce.
    // thread = (mgrp = tid/32, c = tid%32), handles channels c and c+32.
    {
        const int c = tid & 31;
        const int mg = tid >> 5;  // 0..7
        for (int p = 0; p < 2; ++p) {
            const int ml = p * 8 + mg;
            float wkA[KK], wkB[KK];
            #pragma unroll
            for (int k = 0; k < KK; ++k) { wkA[k] = 0.f; wkB[k] = 0.f; }
            const unsigned vm = sm.vmask[ml];
            int cnt = 0;
            #pragma unroll 4
            for (int h = 0; h < HN; ++h) {
                const int si = sm.sidx[ml][h];
                const float* fp = s_feats + (size_t)si * CC;
                const float fA = __ldg(fp + c);
                const float fB = __ldg(fp + c + 32);
                // feat sum across all 64 channels (this warp covers them all)
                float s = fA + fB;
                #pragma unroll
                for (int off = 16; off > 0; off >>= 1)
                    s += __shfl_xor_sync(0xffffffffu, s, off);
                if (((vm >> h) & 1u) && s > 0.0f) cnt++;

                const float4* ip = reinterpret_cast<const float4*>(sm.infl[ml][h]);
                const float4 i0 = ip[0], i1 = ip[1], i2 = ip[2], i3 = ip[3];
                wkA[0]  += i0.x * fA;  wkB[0]  += i0.x * fB;
                wkA[1]  += i0.y * fA;  wkB[1]  += i0.y * fB;
                wkA[2]  += i0.z * fA;  wkB[2]  += i0.z * fB;
                wkA[3]  += i0.w * fA;  wkB[3]  += i0.w * fB;
                wkA[4]  += i1.x * fA;  wkB[4]  += i1.x * fB;
                wkA[5]  += i1.y * fA;  wkB[5]  += i1.y * fB;
                wkA[6]  += i1.z * fA;  wkB[6]  += i1.z * fB;
                wkA[7]  += i1.w * fA;  wkB[7]  += i1.w * fB;
                wkA[8]  += i2.x * fA;  wkB[8]  += i2.x * fB;
                wkA[9]  += i2.y * fA;  wkB[9]  += i2.y * fB;
                wkA[10] += i2.z * fA;  wkB[10] += i2.z * fB;
                wkA[11] += i2.w * fA;  wkB[11] += i2.w * fB;
                wkA[12] += i3.x * fA;  wkB[12] += i3.x * fB;
                wkA[13] += i3.y * fA;  wkB[13] += i3.y * fB;
                wkA[14] += i3.z * fA;  wkB[14] += i3.z * fB;
            }
            #pragma unroll
            for (int k = 0; k < KK; ++k) {
                sm.weighted[ml][k][c]      = wkA[k];
                sm.weighted[ml][k][c + 32] = wkB[k];
            }
            if (c == 0) sm.nnum[ml] = (float)(cnt > 0 ? cnt : 1);
        }
    }
    __syncthreads();

    // ---- Stage C: out[m][d] = (sum_{k,c} weighted[m][k][c] * W[k][c][d]) / nnum
    // thread = (mC = tid/16, dq = tid%16) -> one query, 4 output channels.
    {
        const int mC = tid >> 4;   // 0..15
        const int dq = tid & 15;   // d = 4*dq .. 4*dq+3
        float4 acc = make_float4(0.f, 0.f, 0.f, 0.f);
        const float4* W4 = reinterpret_cast<const float4*>(weights);
        for (int k = 0; k < KK; ++k) {
            const float4* wrow = reinterpret_cast<const float4*>(sm.weighted[mC][k]);
            const int kbase = k * CC;  // row index into W[k][c][*]
            #pragma unroll
            for (int cq = 0; cq < CC / 4; ++cq) {
                const float4 a = wrow[cq];
                const int cb = kbase + cq * 4;
                const float4 b0 = W4[(cb + 0) * (CC / 4) + dq];
                const float4 b1 = W4[(cb + 1) * (CC / 4) + dq];
                const float4 b2 = W4[(cb + 2) * (CC / 4) + dq];
                const float4 b3 = W4[(cb + 3) * (CC / 4) + dq];
                acc.x += a.x * b0.x + a.y * b1.x + a.z * b2.x + a.w * b3.x;
                acc.y += a.x * b0.y + a.y * b1.y + a.z * b2.y + a.w * b3.y;
                acc.z += a.x * b0.z + a.y * b1.z + a.z * b2.z + a.w * b3.z;
                acc.w += a.x * b0.w + a.y * b1.w + a.z * b2.w + a.w * b3.w;
            }
        }
        const int m = m0 + mC;
        if (m < M) {
            const float nn = sm.nnum[mC];
            float4 o;
            o.x = acc.x / nn;
            o.y = acc.y / nn;
            o.z = acc.z / nn;
            o.w = acc.w / nn;
            reinterpret_cast<float4*>(out)[(size_t)m * (CC / 4) + dq] = o;
        }
    }
}

extern "C" void kernel_launch(void* const* d_in, const int* in_sizes, int n_in,
                              void* d_out, int out_size)
{
    const float* q_points      = (const float*)d_in[0];  // (M,3)
    const float* s_points      = (const float*)d_in[1];  // (N,3)
    const float* s_feats       = (const float*)d_in[2];  // (N,64)
    const void*  neighbor_idx  = d_in[3];                // (M,32) int32 or int64
    const float* kernel_points = (const float*)d_in[4];  // (15,3)
    const float* weights       = (const float*)d_in[5];  // (15,64,64)
    float*       out           = (float*)d_out;          // (M,64)

    const int M = in_sizes[0] / 3;
    const int N = in_sizes[1] / 3;

    // ---- dtype probe for neighbor_indices ----
    // If int64 (values <= N < 2^31), every odd 32-bit word is 0.
    // If int32, odd words are random indices, overwhelmingly nonzero.
    init_flag_kernel<<<1, 1>>>();
    const int nwords = 65536;  // M*H >= 65536 int32 words in both interpretations
    probe_idx_kernel<<<(nwords / 2 + 255) / 256, 256>>>((const int*)neighbor_idx, nwords);

    cudaFuncSetAttribute(kpconv_kernel,
                         cudaFuncAttributeMaxDynamicSharedMemorySize,
                         (int)sizeof(Smem));

    const int blocks = (M + QT - 1) / QT;
    kpconv_kernel<<<blocks, NTHREADS, sizeof(Smem)>>>(
        q_points, s_points, s_feats, neighbor_idx, kernel_points, weights,
        out, M, N);
}

// round 3
// speedup vs baseline: 1.7220x; 1.7220x over previous
#include <cuda_runtime.h>
#include <cstdint>

// KPConv fused: M=50000 queries, H=32 neighbors, K=15 kernel pts, Cin=Cout=64.
// Block = 16 queries. Launch 1: per-source-row feature sums (for neighbor
// count). Launch 2: fused influence + neighbor-weighted sum + GEMM + normalize.

#define QT 16
#define HN 32
#define KK 15
#define KP 16        // K padded to 16 for float4 rows
#define CC 64
#define NTHREADS 256
#define MAXN 65536

__device__ float g_colsum[MAXN];   // per-source-row sum of features

// warp per source row: lane sums channels (lane, lane+32), butterfly-reduce.
__global__ void colsum_kernel(const float* __restrict__ s_feats, int N) {
    const int lane = threadIdx.x & 31;
    const int row = blockIdx.x * 8 + (threadIdx.x >> 5);
    if (row >= N) return;
    const float* fp = s_feats + (size_t)row * CC;
    float s = fp[lane] + fp[lane + 32];
    #pragma unroll
    for (int off = 16; off > 0; off >>= 1)
        s += __shfl_xor_sync(0xffffffffu, s, off);
    if (lane == 0) g_colsum[row] = s;
}

struct __align__(16) Smem {
    float infl[QT][HN][KP];     // 32768 B; reused as GEMM partials in stage C
    float weighted[QT][KK][CC]; // 61440 B
    float kp[KK][3];
    int   sidx[QT][HN];
    float nnum[QT];
};

__global__ __launch_bounds__(NTHREADS, 2)
void kpconv_kernel(const float* __restrict__ q_points,
                   const float* __restrict__ s_points,
                   const float* __restrict__ s_feats,
                   const void* __restrict__ nbr_idx_raw,
                   const float* __restrict__ kernel_points,
                   const float* __restrict__ weights,
                   float* __restrict__ out,
                   int M, int N)
{
    extern __shared__ __align__(16) char smem_raw[];
    Smem& sm = *reinterpret_cast<Smem*>(smem_raw);
    const int tid = threadIdx.x;
    const int m0 = blockIdx.x * QT;

    // ---- dtype probe: int64 indices (values <= N) have zero odd words ----
    const int* iw = reinterpret_cast<const int*>(nbr_idx_raw);
    int oddbits = iw[2 * tid + 1] | iw[2 * (tid + NTHREADS) + 1];
    if (tid < KK * 3)
        reinterpret_cast<float*>(sm.kp)[tid] = kernel_points[tid];
    const int idx64 = !__syncthreads_or(oddbits != 0);

    // ---- Stage A: influence, indices, neighbor count ----
    {
        const int lane = tid & 31;       // = h
        const int wgrp = tid >> 5;
        #pragma unroll
        for (int p = 0; p < 2; ++p) {
            const int ml = p * 8 + wgrp;
            const int m = m0 + ml;
            bool valid = false;
            int si = 0;
            float rx = 0.f, ry = 0.f, rz = 0.f, cs = 0.f;
            if (m < M) {
                long long gi;
                if (idx64)
                    gi = reinterpret_cast<const long long*>(nbr_idx_raw)[(long long)m * HN + lane];
                else
                    gi = reinterpret_cast<const int*>(nbr_idx_raw)[(long long)m * HN + lane];
                if (gi < (long long)N) { valid = true; si = (int)gi; }
            }
            sm.sidx[ml][lane] = si;
            if (valid) {
                rx = s_points[si * 3 + 0] - q_points[m * 3 + 0];
                ry = s_points[si * 3 + 1] - q_points[m * 3 + 1];
                rz = s_points[si * 3 + 2] - q_points[m * 3 + 2];
                cs = g_colsum[si];
            }
            #pragma unroll
            for (int k = 0; k < KK; ++k) {
                float dx = rx - sm.kp[k][0];
                float dy = ry - sm.kp[k][1];
                float dz = rz - sm.kp[k][2];
                float d2 = dx * dx + dy * dy + dz * dz;
                float inf = fmaxf(1.0f - sqrtf(d2), 0.0f);  // SIGMA = 1
                sm.infl[ml][lane][k] = valid ? inf : 0.0f;
            }
            sm.infl[ml][lane][KK] = 0.0f;  // pad
            unsigned bal = __ballot_sync(0xffffffffu, valid && cs > 0.0f);
            if (lane == 0) {
                int cnt = __popc(bal);
                sm.nnum[ml] = (float)(cnt > 0 ? cnt : 1);
            }
        }
    }
    __syncthreads();

    // ---- Stage B: weighted[m][k][c] = sum_h infl[m][h][k] * feat[si][c] ----
    // thread = (mg = tid/32, c = tid%32); channels c and c+32.
    {
        const int c = tid & 31;
        const int mg = tid >> 5;
        for (int p = 0; p < 2; ++p) {
            const int ml = p * 8 + mg;
            float wkA[KK], wkB[KK];
            #pragma unroll
            for (int k = 0; k < KK; ++k) { wkA[k] = 0.f; wkB[k] = 0.f; }
            #pragma unroll 4
            for (int h = 0; h < HN; ++h) {
                const int si = sm.sidx[ml][h];
                const float* fp = s_feats + (size_t)si * CC;
                const float fA = __ldg(fp + c);
                const float fB = __ldg(fp + c + 32);
                const float4* ip = reinterpret_cast<const float4*>(sm.infl[ml][h]);
                const float4 i0 = ip[0], i1 = ip[1], i2 = ip[2], i3 = ip[3];
                wkA[0]  += i0.x * fA;  wkB[0]  += i0.x * fB;
                wkA[1]  += i0.y * fA;  wkB[1]  += i0.y * fB;
                wkA[2]  += i0.z * fA;  wkB[2]  += i0.z * fB;
                wkA[3]  += i0.w * fA;  wkB[3]  += i0.w * fB;
                wkA[4]  += i1.x * fA;  wkB[4]  += i1.x * fB;
                wkA[5]  += i1.y * fA;  wkB[5]  += i1.y * fB;
                wkA[6]  += i1.z * fA;  wkB[6]  += i1.z * fB;
                wkA[7]  += i1.w * fA;  wkB[7]  += i1.w * fB;
                wkA[8]  += i2.x * fA;  wkB[8]  += i2.x * fB;
                wkA[9]  += i2.y * fA;  wkB[9]  += i2.y * fB;
                wkA[10] += i2.z * fA;  wkB[10] += i2.z * fB;
                wkA[11] += i2.w * fA;  wkB[11] += i2.w * fB;
                wkA[12] += i3.x * fA;  wkB[12] += i3.x * fB;
                wkA[13] += i3.y * fA;  wkB[13] += i3.y * fB;
                wkA[14] += i3.z * fA;  wkB[14] += i3.z * fB;
            }
            #pragma unroll
            for (int k = 0; k < KK; ++k) {
                sm.weighted[ml][k][c]      = wkA[k];
                sm.weighted[ml][k][c + 32] = wkB[k];
            }
        }
    }
    __syncthreads();

    // ---- Stage C: out[m][d] = (sum_{k,c} weighted[m][k][c]*W[k][c][d]) / nnum
    // thread = (ks = tid/64, qg = (tid/16)%4, dq = tid%16).
    // k split over 4 groups; each W float4 load reused across 4 queries.
    // Partials go into the (dead) infl region: part[ks][q][dq] float4 = 16 KB.
    {
        float4* part = reinterpret_cast<float4*>(sm.infl);
        const int ks = tid >> 6;
        const int qg = (tid >> 4) & 3;
        const int dq = tid & 15;
        const int kbeg = ks * 4;
        const int kend = (ks == 3) ? KK : kbeg + 4;
        float4 acc[4];
        #pragma unroll
        for (int qi = 0; qi < 4; ++qi) acc[qi] = make_float4(0.f, 0.f, 0.f, 0.f);

        for (int k = kbeg; k < kend; ++k) {
            const float4* wk = reinterpret_cast<const float4*>(weights + (size_t)k * CC * CC);
            #pragma unroll
            for (int cq = 0; cq < CC / 4; ++cq) {
                const float4 b0 = __ldg(&wk[(cq * 4 + 0) * (CC / 4) + dq]);
                const float4 b1 = __ldg(&wk[(cq * 4 + 1) * (CC / 4) + dq]);
                const float4 b2 = __ldg(&wk[(cq * 4 + 2) * (CC / 4) + dq]);
                const float4 b3 = __ldg(&wk[(cq * 4 + 3) * (CC / 4) + dq]);
                #pragma unroll
                for (int qi = 0; qi < 4; ++qi) {
                    const float4 a =
                        reinterpret_cast<const float4*>(sm.weighted[qg * 4 + qi][k])[cq];
                    acc[qi].x += a.x * b0.x + a.y * b1.x + a.z * b2.x + a.w * b3.x;
                    acc[qi].y += a.x * b0.y + a.y * b1.y + a.z * b2.y + a.w * b3.y;
                    acc[qi].z += a.x * b0.z + a.y * b1.z + a.z * b2.z + a.w * b3.z;
                    acc[qi].w += a.x * b0.w + a.y * b1.w + a.z * b2.w + a.w * b3.w;
                }
            }
        }
        #pragma unroll
        for (int qi = 0; qi < 4; ++qi)
            part[(ks * QT + qg * 4 + qi) * (CC / 4) + dq] = acc[qi];
    }
    __syncthreads();

    // ---- Reduce partials over the 4 k-groups, normalize, store ----
    {
        float4* part = reinterpret_cast<float4*>(sm.infl);
        const int q = tid >> 4;
        const int dq = tid & 15;
        const int m = m0 + q;
        if (m < M) {
            float4 r0 = part[(0 * QT + q) * (CC / 4) + dq];
            float4 r1 = part[(1 * QT + q) * (CC / 4) + dq];
            float4 r2 = part[(2 * QT + q) * (CC / 4) + dq];
            float4 r3 = part[(3 * QT + q) * (CC / 4) + dq];
            const float nn = sm.nnum[q];
            float4 o;
            o.x = (r0.x + r1.x + r2.x + r3.x) / nn;
            o.y = (r0.y + r1.y + r2.y + r3.y) / nn;
            o.z = (r0.z + r1.z + r2.z + r3.z) / nn;
            o.w = (r0.w + r1.w + r2.w + r3.w) / nn;
            reinterpret_cast<float4*>(out)[(size_t)m * (CC / 4) + dq] = o;
        }
    }
}

extern "C" void kernel_launch(void* const* d_in, const int* in_sizes, int n_in,
                              void* d_out, int out_size)
{
    const float* q_points      = (const float*)d_in[0];  // (M,3)
    const float* s_points      = (const float*)d_in[1];  // (N,3)
    const float* s_feats       = (const float*)d_in[2];  // (N,64)
    const void*  neighbor_idx  = d_in[3];                // (M,32) int32 or int64
    const float* kernel_points = (const float*)d_in[4];  // (15,3)
    const float* weights       = (const float*)d_in[5];  // (15,64,64)
    float*       out           = (float*)d_out;          // (M,64)

    const int M = in_sizes[0] / 3;
    const int N = in_sizes[1] / 3;

    colsum_kernel<<<(N + 7) / 8, NTHREADS>>>(s_feats, N);

    cudaFuncSetAttribute(kpconv_kernel,
                         cudaFuncAttributeMaxDynamicSharedMemorySize,
                         (int)sizeof(Smem));
    const int blocks = (M + QT - 1) / QT;
    kpconv_kernel<<<blocks, NTHREADS, sizeof(Smem)>>>(
        q_points, s_points, s_feats, neighbor_idx, kernel_points, weights,
        out, M, N);
}

// round 5
// speedup vs baseline: 1.8293x; 1.0624x over previous
#include <cuda_runtime.h>
#include <cstdint>

// KPConv fused, f32x2 (FFMA2) version, explicit 64-bit shared accesses.
// M=50000, H=32 neighbors, K=15 kernel pts, Cin=Cout=64. 16 queries/block.

#define QT 16
#define HN 32
#define KK 15
#define KP 16        // K padded to 16
#define CC 64
#define NTHREADS 256
#define MAXN 65536
#define WTP 18       // wT q-stride (floats)
#define PTP 18       // part q-stride (floats, even => 8B-aligned pairs)

typedef unsigned long long ull;

__device__ __forceinline__ ull pack2(float lo, float hi) {
    ull r; asm("mov.b64 %0, {%1, %2};" : "=l"(r) : "f"(lo), "f"(hi)); return r;
}
__device__ __forceinline__ void fma2(ull& d, ull a, ull b) {
    asm("fma.rn.f32x2 %0, %1, %2, %0;" : "+l"(d) : "l"(a), "l"(b));
}
__device__ __forceinline__ float2 unpack2(ull v) {
    float2 r; asm("mov.b64 {%0, %1}, %2;" : "=f"(r.x), "=f"(r.y) : "l"(v)); return r;
}
// Explicit 64-bit shared ld/st: compiler cannot widen these to 128-bit.
__device__ __forceinline__ ull lds64(uint32_t a) {
    ull r; asm("ld.shared.b64 %0, [%1];" : "=l"(r) : "r"(a)); return r;
}
__device__ __forceinline__ void sts64(uint32_t a, ull v) {
    asm("st.shared.b64 [%0], %1;" :: "r"(a), "l"(v) : "memory");
}

__device__ float g_colsum[MAXN];   // per-source-row feature sum

__global__ void colsum_kernel(const float* __restrict__ s_feats, int N) {
    const int lane = threadIdx.x & 31;
    const int row = blockIdx.x * 8 + (threadIdx.x >> 5);
    if (row >= N) return;
    const float* fp = s_feats + (size_t)row * CC;
    float s = fp[lane] + fp[lane + 32];
    #pragma unroll
    for (int off = 16; off > 0; off >>= 1)
        s += __shfl_xor_sync(0xffffffffu, s, off);
    if (lane == 0) g_colsum[row] = s;
}

struct __align__(16) Smem {
    union {
        struct {
            float infl[QT][HN][KP];     // 32768 B (live: stages A,B)
            int   sidx[QT][HN];         // 2048 B
            float kp[KK][3];
        } a;
        float part[8][CC][PTP];         // 36864 B (live: stage C reduce)
    } u;
    float wT[KK][CC][WTP];              // 69120 B: weighted, transposed [k][c][q]
    float nnum[QT];
};

__global__ __launch_bounds__(NTHREADS, 2)
void kpconv_kernel(const float* __restrict__ q_points,
                   const float* __restrict__ s_points,
                   const float* __restrict__ s_feats,
                   const void* __restrict__ nbr_idx_raw,
                   const float* __restrict__ kernel_points,
                   const float* __restrict__ weights,
                   float* __restrict__ out,
                   int M, int N)
{
    extern __shared__ __align__(16) char smem_raw[];
    Smem& sm = *reinterpret_cast<Smem*>(smem_raw);
    const int tid = threadIdx.x;
    const int m0 = blockIdx.x * QT;

    // ---- dtype probe: int64 indices (<= N) have zero odd 32-bit words ----
    const int* iw = reinterpret_cast<const int*>(nbr_idx_raw);
    int oddbits = iw[2 * tid + 1] | iw[2 * (tid + NTHREADS) + 1];
    if (tid < KK * 3)
        reinterpret_cast<float*>(sm.u.a.kp)[tid] = kernel_points[tid];
    const int idx64 = !__syncthreads_or(oddbits != 0);

    // ---- Stage A: influence, indices, neighbor count ----
    {
        const int lane = tid & 31;     // h
        const int wgrp = tid >> 5;
        #pragma unroll
        for (int p = 0; p < 2; ++p) {
            const int ml = p * 8 + wgrp;
            const int m = m0 + ml;
            bool valid = false;
            int si = 0;
            float rx = 0.f, ry = 0.f, rz = 0.f, cs = 0.f;
            if (m < M) {
                long long gi;
                if (idx64)
                    gi = reinterpret_cast<const long long*>(nbr_idx_raw)[(long long)m * HN + lane];
                else
                    gi = reinterpret_cast<const int*>(nbr_idx_raw)[(long long)m * HN + lane];
                if (gi < (long long)N) { valid = true; si = (int)gi; }
            }
            sm.u.a.sidx[ml][lane] = si;
            if (valid) {
                rx = s_points[si * 3 + 0] - q_points[m * 3 + 0];
                ry = s_points[si * 3 + 1] - q_points[m * 3 + 1];
                rz = s_points[si * 3 + 2] - q_points[m * 3 + 2];
                cs = g_colsum[si];
            }
            #pragma unroll
            for (int k = 0; k < KK; ++k) {
                float dx = rx - sm.u.a.kp[k][0];
                float dy = ry - sm.u.a.kp[k][1];
                float dz = rz - sm.u.a.kp[k][2];
                float d2 = dx * dx + dy * dy + dz * dz;
                float inf = fmaxf(1.0f - sqrtf(d2), 0.0f);  // SIGMA = 1
                sm.u.a.infl[ml][lane][k] = valid ? inf : 0.0f;
            }
            sm.u.a.infl[ml][lane][KK] = 0.0f;  // pad k=15
            unsigned bal = __ballot_sync(0xffffffffu, valid && cs > 0.0f);
            if (lane == 0) {
                int cnt = __popc(bal);
                sm.nnum[ml] = (float)(cnt > 0 ? cnt : 1);
            }
        }
    }
    __syncthreads();

    // ---- Stage B (FFMA2): wT[k][c][q] = sum_h infl[q][h][k] * feat[si][c] ----
    // thread = (mg = warp, c = lane); handles channels c and c+32.
    {
        const int c = tid & 31;
        const int mg = tid >> 5;
        for (int p = 0; p < 2; ++p) {
            const int ml = p * 8 + mg;
            ull wA[8], wB[8];
            #pragma unroll
            for (int j = 0; j < 8; ++j) { wA[j] = 0ull; wB[j] = 0ull; }
            const uint32_t infl_s =
                (uint32_t)__cvta_generic_to_shared(&sm.u.a.infl[ml][0][0]);
            #pragma unroll 4
            for (int h = 0; h < HN; ++h) {
                const int si = sm.u.a.sidx[ml][h];
                const float* fp = s_feats + (size_t)si * CC;
                const float fA = __ldg(fp + c);
                const float fB = __ldg(fp + c + 32);
                const ull a2 = pack2(fA, fA);
                const ull b2 = pack2(fB, fB);
                const uint32_t ia = infl_s + h * (KP * 4);   // 64B per row
                const ull v0 = lds64(ia);
                const ull v1 = lds64(ia + 8);
                const ull v2 = lds64(ia + 16);
                const ull v3 = lds64(ia + 24);
                const ull v4 = lds64(ia + 32);
                const ull v5 = lds64(ia + 40);
                const ull v6 = lds64(ia + 48);
                const ull v7 = lds64(ia + 56);
                fma2(wA[0], v0, a2);  fma2(wB[0], v0, b2);
                fma2(wA[1], v1, a2);  fma2(wB[1], v1, b2);
                fma2(wA[2], v2, a2);  fma2(wB[2], v2, b2);
                fma2(wA[3], v3, a2);  fma2(wB[3], v3, b2);
                fma2(wA[4], v4, a2);  fma2(wB[4], v4, b2);
                fma2(wA[5], v5, a2);  fma2(wB[5], v5, b2);
                fma2(wA[6], v6, a2);  fma2(wB[6], v6, b2);
                fma2(wA[7], v7, a2);  fma2(wB[7], v7, b2);
            }
            #pragma unroll
            for (int j = 0; j < 7; ++j) {
                float2 tA = unpack2(wA[j]);
                float2 tB = unpack2(wB[j]);
                sm.wT[2 * j][c][ml]          = tA.x;
                sm.wT[2 * j + 1][c][ml]      = tA.y;
                sm.wT[2 * j][c + 32][ml]     = tB.x;
                sm.wT[2 * j + 1][c + 32][ml] = tB.y;
            }
            { // k = 14 (pair hi-half is the zero pad, dropped)
                float2 tA = unpack2(wA[7]);
                float2 tB = unpack2(wB[7]);
                sm.wT[14][c][ml]      = tA.x;
                sm.wT[14][c + 32][ml] = tB.x;
            }
        }
    }
    __syncthreads();

    // ---- Stage C (FFMA2): partial GEMM. thread = (ks=warp, g, dq).
    // ks covers k in {2ks, 2ks+1} (ks=7 -> k=14 only).
    // g = query octet [8g, 8g+8); dq = 4 output dims 4dq..4dq+3.
    // Each W float4 load feeds 8 queries; A pairs via explicit LDS.64
    // (warp-broadcast: lanes within a half-warp hit the same address).
    {
        const int ks = tid >> 5;
        const int g  = (tid >> 4) & 1;
        const int dq = tid & 15;
        ull acc[4][4];
        #pragma unroll
        for (int i = 0; i < 4; ++i)
            #pragma unroll
            for (int j = 0; j < 4; ++j) acc[i][j] = 0ull;

        const int kend = (2 * ks + 2 < KK) ? 2 * ks + 2 : KK;
        for (int k = 2 * ks; k < kend; ++k) {
            const float4* wk =
                reinterpret_cast<const float4*>(weights + (size_t)k * CC * CC) + dq;
            const uint32_t wt_s =
                (uint32_t)__cvta_generic_to_shared(&sm.wT[k][0][8 * g]);
            #pragma unroll 4
            for (int c = 0; c < CC; ++c) {
                const float4 b = __ldg(wk + c * (CC / 4));
                const ull bx = pack2(b.x, b.x);
                const ull by = pack2(b.y, b.y);
                const ull bz = pack2(b.z, b.z);
                const ull bw = pack2(b.w, b.w);
                const uint32_t a = wt_s + c * (WTP * 4);
                const ull a01 = lds64(a);
                const ull a23 = lds64(a + 8);
                const ull a45 = lds64(a + 16);
                const ull a67 = lds64(a + 24);
                fma2(acc[0][0], a01, bx); fma2(acc[0][1], a01, by);
                fma2(acc[0][2], a01, bz); fma2(acc[0][3], a01, bw);
                fma2(acc[1][0], a23, bx); fma2(acc[1][1], a23, by);
                fma2(acc[1][2], a23, bz); fma2(acc[1][3], a23, bw);
                fma2(acc[2][0], a45, bx); fma2(acc[2][1], a45, by);
                fma2(acc[2][2], a45, bz); fma2(acc[2][3], a45, bw);
                fma2(acc[3][0], a67, bx); fma2(acc[3][1], a67, by);
                fma2(acc[3][2], a67, bz); fma2(acc[3][3], a67, bw);
            }
        }
        __syncthreads();   // infl region dead; safe to overwrite with partials
        const uint32_t part_s =
            (uint32_t)__cvta_generic_to_shared(&sm.u.part[ks][0][0]);
        #pragma unroll
        for (int i = 0; i < 4; ++i) {
            #pragma unroll
            for (int j = 0; j < 4; ++j) {
                // q offset 8g+2i is even and PTP is even => 8B aligned
                sts64(part_s + ((4 * dq + j) * PTP + 8 * g + 2 * i) * 4,
                      acc[i][j]);
            }
        }
    }
    __syncthreads();

    // ---- Reduce over 8 k-groups, normalize, store ----
    {
        const int q = tid >> 4;
        const int dq = tid & 15;
        const int m = m0 + q;
        if (m < M) {
            float ox = 0.f, oy = 0.f, oz = 0.f, ow = 0.f;
            #pragma unroll
            for (int ks = 0; ks < 8; ++ks) {
                ox += sm.u.part[ks][4 * dq + 0][q];
                oy += sm.u.part[ks][4 * dq + 1][q];
                oz += sm.u.part[ks][4 * dq + 2][q];
                ow += sm.u.part[ks][4 * dq + 3][q];
            }
            const float nn = sm.nnum[q];
            float4 o;
            o.x = ox / nn; o.y = oy / nn; o.z = oz / nn; o.w = ow / nn;
            reinterpret_cast<float4*>(out)[(size_t)m * (CC / 4) + dq] = o;
        }
    }
}

extern "C" void kernel_launch(void* const* d_in, const int* in_sizes, int n_in,
                              void* d_out, int out_size)
{
    const float* q_points      = (const float*)d_in[0];  // (M,3)
    const float* s_points      = (const float*)d_in[1];  // (N,3)
    const float* s_feats       = (const float*)d_in[2];  // (N,64)
    const void*  neighbor_idx  = d_in[3];                // (M,32) int32/int64
    const float* kernel_points = (const float*)d_in[4];  // (15,3)
    const float* weights       = (const float*)d_in[5];  // (15,64,64)
    float*       out           = (float*)d_out;          // (M,64)

    const int M = in_sizes[0] / 3;
    const int N = in_sizes[1] / 3;

    colsum_kernel<<<(N + 7) / 8, NTHREADS>>>(s_feats, N);

    cudaFuncSetAttribute(kpconv_kernel,
                         cudaFuncAttributeMaxDynamicSharedMemorySize,
                         (int)sizeof(Smem));
    const int blocks = (M + QT - 1) / QT;
    kpconv_kernel<<<blocks, NTHREADS, sizeof(Smem)>>>(
        q_points, s_points, s_feats, neighbor_idx, kernel_points, weights,
        out, M, N);
}

// round 6
// speedup vs baseline: 2.2521x; 1.2311x over previous
#include <cuda_runtime.h>
#include <cstdint>

// KPConv fused, FFMA2 + neighbor compaction + 16-query W reuse.
// M=50000, H=32, K=15 kernel pts, Cin=Cout=64. 16 queries/block, 256 thr.

#define QT 16
#define HN 32
#define KK 15
#define KP 16
#define CC 64
#define NTHREADS 256
#define MAXN 65536
#define WTP 18       // wT q-stride (floats)
#define PTP 18       // part q-stride (floats)

typedef unsigned long long ull;

__device__ __forceinline__ ull pack2(float lo, float hi) {
    ull r; asm("mov.b64 %0, {%1, %2};" : "=l"(r) : "f"(lo), "f"(hi)); return r;
}
__device__ __forceinline__ void fma2(ull& d, ull a, ull b) {
    asm("fma.rn.f32x2 %0, %1, %2, %0;" : "+l"(d) : "l"(a), "l"(b));
}
__device__ __forceinline__ float2 unpack2(ull v) {
    float2 r; asm("mov.b64 {%0, %1}, %2;" : "=f"(r.x), "=f"(r.y) : "l"(v)); return r;
}
__device__ __forceinline__ ull lds64(uint32_t a) {
    ull r; asm("ld.shared.b64 %0, [%1];" : "=l"(r) : "r"(a)); return r;
}
__device__ __forceinline__ void sts64(uint32_t a, ull v) {
    asm("st.shared.b64 [%0], %1;" :: "r"(a), "l"(v) : "memory");
}

__device__ float g_colsum[MAXN];

__global__ void colsum_kernel(const float* __restrict__ s_feats, int N) {
    const int lane = threadIdx.x & 31;
    const int row = blockIdx.x * 8 + (threadIdx.x >> 5);
    if (row >= N) return;
    const float* fp = s_feats + (size_t)row * CC;
    float s = fp[lane] + fp[lane + 32];
    #pragma unroll
    for (int off = 16; off > 0; off >>= 1)
        s += __shfl_xor_sync(0xffffffffu, s, off);
    if (lane == 0) g_colsum[row] = s;
}

struct __align__(16) Smem {
    union {
        struct {
            float infl[QT][HN][KP];     // compacted influence rows
            int   sidx[QT][HN];         // compacted source indices
            float kp[KK][3];
            int   cnt[QT];              // # neighbors with nonzero influence
        } a;
        float part[8][CC][PTP];         // stage-C partials (overwrites a)
    } u;
    float wT[KK][CC][WTP];              // weighted, transposed [k][c][q]
    float nnum[QT];
};

__global__ __launch_bounds__(NTHREADS, 2)
void kpconv_kernel(const float* __restrict__ q_points,
                   const float* __restrict__ s_points,
                   const float* __restrict__ s_feats,
                   const void* __restrict__ nbr_idx_raw,
                   const float* __restrict__ kernel_points,
                   const float* __restrict__ weights,
                   float* __restrict__ out,
                   int M, int N)
{
    extern __shared__ __align__(16) char smem_raw[];
    Smem& sm = *reinterpret_cast<Smem*>(smem_raw);
    const int tid = threadIdx.x;
    const int m0 = blockIdx.x * QT;

    // ---- dtype probe: int64 indices (<= N) have zero odd 32-bit words ----
    const int* iw = reinterpret_cast<const int*>(nbr_idx_raw);
    int oddbits = iw[2 * tid + 1] | iw[2 * (tid + NTHREADS) + 1];
    if (tid < KK * 3)
        reinterpret_cast<float*>(sm.u.a.kp)[tid] = kernel_points[tid];
    const int idx64 = !__syncthreads_or(oddbits != 0);

    // ---- Stage A: influence + compaction + neighbor count ----
    {
        const int lane = tid & 31;     // h
        const int wgrp = tid >> 5;
        const unsigned lt = (1u << lane) - 1u;
        #pragma unroll
        for (int p = 0; p < 2; ++p) {
            const int ml = p * 8 + wgrp;
            const int m = m0 + ml;
            bool valid = false;
            int si = 0;
            float rx = 0.f, ry = 0.f, rz = 0.f, cs = 0.f;
            if (m < M) {
                long long gi;
                if (idx64)
                    gi = reinterpret_cast<const long long*>(nbr_idx_raw)[(long long)m * HN + lane];
                else
                    gi = reinterpret_cast<const int*>(nbr_idx_raw)[(long long)m * HN + lane];
                if (gi < (long long)N) { valid = true; si = (int)gi; }
            }
            if (valid) {
                rx = s_points[si * 3 + 0] - q_points[m * 3 + 0];
                ry = s_points[si * 3 + 1] - q_points[m * 3 + 1];
                rz = s_points[si * 3 + 2] - q_points[m * 3 + 2];
                cs = g_colsum[si];
            }
            float inf[KK];
            float mx = 0.f;
            #pragma unroll
            for (int k = 0; k < KK; ++k) {
                float dx = rx - sm.u.a.kp[k][0];
                float dy = ry - sm.u.a.kp[k][1];
                float dz = rz - sm.u.a.kp[k][2];
                float d2 = dx * dx + dy * dy + dz * dz;
                inf[k] = fmaxf(1.0f - sqrtf(d2), 0.0f);   // SIGMA = 1
                mx = fmaxf(mx, inf[k]);
            }
            const bool any = valid && (mx > 0.0f);
            const unsigned amask = __ballot_sync(0xffffffffu, any);
            if (any) {
                const int pos = __popc(amask & lt);
                sm.u.a.sidx[ml][pos] = si;
                #pragma unroll
                for (int k = 0; k < KK; ++k)
                    sm.u.a.infl[ml][pos][k] = inf[k];
                sm.u.a.infl[ml][pos][KK] = 0.0f;   // pad k=15
            }
            const unsigned nbal = __ballot_sync(0xffffffffu, valid && cs > 0.0f);
            if (lane == 0) {
                sm.u.a.cnt[ml] = __popc(amask);
                int c2 = __popc(nbal);
                sm.nnum[ml] = (float)(c2 > 0 ? c2 : 1);
            }
        }
    }
    __syncthreads();

    // ---- Stage B (FFMA2): wT[k][c][q] = sum_h' infl[q][h'][k]*feat[si][c] ----
    // thread = (mg = warp, c = lane); channels c and c+32; h' over compacted.
    {
        const int c = tid & 31;
        const int mg = tid >> 5;
        for (int p = 0; p < 2; ++p) {
            const int ml = p * 8 + mg;
            const int cnt = sm.u.a.cnt[ml];
            ull wA[8], wB[8];
            #pragma unroll
            for (int j = 0; j < 8; ++j) { wA[j] = 0ull; wB[j] = 0ull; }
            const uint32_t infl_s =
                (uint32_t)__cvta_generic_to_shared(&sm.u.a.infl[ml][0][0]);
            for (int h = 0; h < cnt; ++h) {
                const int si = sm.u.a.sidx[ml][h];
                const float* fp = s_feats + (size_t)si * CC;
                const float fA = __ldg(fp + c);
                const float fB = __ldg(fp + c + 32);
                const ull a2 = pack2(fA, fA);
                const ull b2 = pack2(fB, fB);
                const uint32_t ia = infl_s + h * (KP * 4);
                const ull v0 = lds64(ia);
                const ull v1 = lds64(ia + 8);
                const ull v2 = lds64(ia + 16);
                const ull v3 = lds64(ia + 24);
                const ull v4 = lds64(ia + 32);
                const ull v5 = lds64(ia + 40);
                const ull v6 = lds64(ia + 48);
                const ull v7 = lds64(ia + 56);
                fma2(wA[0], v0, a2);  fma2(wB[0], v0, b2);
                fma2(wA[1], v1, a2);  fma2(wB[1], v1, b2);
                fma2(wA[2], v2, a2);  fma2(wB[2], v2, b2);
                fma2(wA[3], v3, a2);  fma2(wB[3], v3, b2);
                fma2(wA[4], v4, a2);  fma2(wB[4], v4, b2);
                fma2(wA[5], v5, a2);  fma2(wB[5], v5, b2);
                fma2(wA[6], v6, a2);  fma2(wB[6], v6, b2);
                fma2(wA[7], v7, a2);  fma2(wB[7], v7, b2);
            }
            #pragma unroll
            for (int j = 0; j < 7; ++j) {
                float2 tA = unpack2(wA[j]);
                float2 tB = unpack2(wB[j]);
                sm.wT[2 * j][c][ml]          = tA.x;
                sm.wT[2 * j + 1][c][ml]      = tA.y;
                sm.wT[2 * j][c + 32][ml]     = tB.x;
                sm.wT[2 * j + 1][c + 32][ml] = tB.y;
            }
            {
                float2 tA = unpack2(wA[7]);
                float2 tB = unpack2(wB[7]);
                sm.wT[14][c][ml]      = tA.x;
                sm.wT[14][c + 32][ml] = tB.x;
            }
        }
    }
    __syncthreads();

    // ---- Stage C (FFMA2): thread = (ks = warp, ch = c parity, dq).
    // Each W float4 load feeds ALL 16 queries (8 pairs in regs).
    // Cross-ch (c even/odd) partial reduced by shfl_xor(16) at the end.
    {
        const int ks = tid >> 5;
        const int ch = (tid >> 4) & 1;
        const int dq = tid & 15;
        ull acc[8][4];
        #pragma unroll
        for (int i = 0; i < 8; ++i)
            #pragma unroll
            for (int j = 0; j < 4; ++j) acc[i][j] = 0ull;

        const int kend = (2 * ks + 2 < KK) ? 2 * ks + 2 : KK;
        for (int k = 2 * ks; k < kend; ++k) {
            const float4* wk =
                reinterpret_cast<const float4*>(weights + (size_t)k * CC * CC) + dq;
            const uint32_t wt_k =
                (uint32_t)__cvta_generic_to_shared(&sm.wT[k][0][0]);
            #pragma unroll 4
            for (int ci = 0; ci < CC / 2; ++ci) {
                const int c = 2 * ci + ch;
                const float4 b = __ldg(wk + c * (CC / 4));
                const ull bx = pack2(b.x, b.x);
                const ull by = pack2(b.y, b.y);
                const ull bz = pack2(b.z, b.z);
                const ull bw = pack2(b.w, b.w);
                const uint32_t abase = wt_k + c * (WTP * 4);
                #pragma unroll
                for (int i = 0; i < 8; ++i) {
                    const ull a = lds64(abase + i * 8);
                    fma2(acc[i][0], a, bx);
                    fma2(acc[i][1], a, by);
                    fma2(acc[i][2], a, bz);
                    fma2(acc[i][3], a, bw);
                }
            }
        }
        // reduce across ch and store partials (u.a region dead since post-B sync)
        const uint32_t part_s =
            (uint32_t)__cvta_generic_to_shared(&sm.u.part[ks][0][0]);
        #pragma unroll
        for (int i = 0; i < 8; ++i) {
            #pragma unroll
            for (int j = 0; j < 4; ++j) {
                const ull o = __shfl_xor_sync(0xffffffffu, acc[i][j], 16);
                float2 s = unpack2(acc[i][j]);
                const float2 t = unpack2(o);
                s.x += t.x; s.y += t.y;
                if (ch == 0)
                    sts64(part_s + ((4 * dq + j) * PTP + 2 * i) * 4,
                          pack2(s.x, s.y));
            }
        }
    }
    __syncthreads();

    // ---- Reduce over 8 k-groups, normalize, store ----
    {
        const int q = tid >> 4;
        const int dq = tid & 15;
        const int m = m0 + q;
        if (m < M) {
            float ox = 0.f, oy = 0.f, oz = 0.f, ow = 0.f;
            #pragma unroll
            for (int ks = 0; ks < 8; ++ks) {
                ox += sm.u.part[ks][4 * dq + 0][q];
                oy += sm.u.part[ks][4 * dq + 1][q];
                oz += sm.u.part[ks][4 * dq + 2][q];
                ow += sm.u.part[ks][4 * dq + 3][q];
            }
            const float nn = sm.nnum[q];
            float4 o;
            o.x = ox / nn; o.y = oy / nn; o.z = oz / nn; o.w = ow / nn;
            reinterpret_cast<float4*>(out)[(size_t)m * (CC / 4) + dq] = o;
        }
    }
}

extern "C" void kernel_launch(void* const* d_in, const int* in_sizes, int n_in,
                              void* d_out, int out_size)
{
    const float* q_points      = (const float*)d_in[0];  // (M,3)
    const float* s_points      = (const float*)d_in[1];  // (N,3)
    const float* s_feats       = (const float*)d_in[2];  // (N,64)
    const void*  neighbor_idx  = d_in[3];                // (M,32) int32/int64
    const float* kernel_points = (const float*)d_in[4];  // (15,3)
    const float* weights       = (const float*)d_in[5];  // (15,64,64)
    float*       out           = (float*)d_out;          // (M,64)

    const int M = in_sizes[0] / 3;
    const int N = in_sizes[1] / 3;

    colsum_kernel<<<(N + 7) / 8, NTHREADS>>>(s_feats, N);

    cudaFuncSetAttribute(kpconv_kernel,
                         cudaFuncAttributeMaxDynamicSharedMemorySize,
                         (int)sizeof(Smem));
    const int blocks = (M + QT - 1) / QT;
    kpconv_kernel<<<blocks, NTHREADS, sizeof(Smem)>>>(
        q_points, s_points, s_feats, neighbor_idx, kernel_points, weights,
        out, M, N);
}